// round 5
// baseline (speedup 1.0000x reference)
#include <cuda_runtime.h>
#include <cuda_fp16.h>
#include <cstdint>

#define NN 100000
#define NE 1600000
#define DD 128
#define SCAN_B 512
#define NSCAN ((NN + SCAN_B - 1) / SCAN_B)

// ---------------- scratch (static device globals) ----------------
__device__ __half g_hs[NN * DD];    // srcnorm-scaled activations, fp16 (gather operand)
__device__ float  g_t[NN * DD];     // aggregated + dstnorm-scaled, fp32 (GEMM input)
__device__ int    g_cin[NN];
__device__ int    g_cout[NN];
__device__ int    g_fill[NN];
__device__ int    g_off[NN + 1];    // CSR row offsets (by dst)
__device__ int    g_csr[NE];        // src ids sorted by dst
__device__ float  g_srcnorm[NN];
__device__ float  g_dstnorm[NN];
__device__ int    g_bsum[NSCAN];
__device__ int    g_bpre[NSCAN];

// ---------------- CSR build ----------------
__global__ void k_zero(int n) {
    int i = blockIdx.x * blockDim.x + threadIdx.x;
    if (i < n) { g_cin[i] = 0; g_cout[i] = 0; g_fill[i] = 0; }
}

__global__ void k_count(const int* __restrict__ src,
                        const int* __restrict__ dst, int E) {
    int i = blockIdx.x * blockDim.x + threadIdx.x;
    if (i < E) {
        atomicAdd(&g_cout[src[i]], 1);
        atomicAdd(&g_cin[dst[i]], 1);
    }
}

__global__ void k_norm(int n) {
    int i = blockIdx.x * blockDim.x + threadIdx.x;
    if (i < n) {
        g_srcnorm[i] = rsqrtf((float)max(g_cout[i], 1));
        g_dstnorm[i] = rsqrtf((float)max(g_cin[i], 1));
    }
}

__global__ void k_scan1(int n) {
    __shared__ int s[SCAN_B];
    int t = threadIdx.x;
    int g = blockIdx.x * SCAN_B + t;
    int v = (g < n) ? g_cin[g] : 0;
    s[t] = v;
    __syncthreads();
    for (int o = 1; o < SCAN_B; o <<= 1) {
        int x = (t >= o) ? s[t - o] : 0;
        __syncthreads();
        s[t] += x;
        __syncthreads();
    }
    if (g < n) g_off[g] = s[t] - v;
    if (t == SCAN_B - 1) g_bsum[blockIdx.x] = s[t];
}

__global__ void k_scan2(int nb, int n) {
    if (threadIdx.x == 0 && blockIdx.x == 0) {
        int run = 0;
        for (int b = 0; b < nb; b++) { g_bpre[b] = run; run += g_bsum[b]; }
        g_off[n] = run;
    }
}

__global__ void k_scan3(int n) {
    int g = blockIdx.x * blockDim.x + threadIdx.x;
    if (g < n) g_off[g] += g_bpre[g / SCAN_B];
}

__global__ void k_fill(const int* __restrict__ src,
                       const int* __restrict__ dst, int E) {
    int e = blockIdx.x * blockDim.x + threadIdx.x;
    if (e < E) {
        int d = dst[e];
        int p = g_off[d] + atomicAdd(&g_fill[d], 1);
        g_csr[p] = src[e];
    }
}

// ---------------- prescale: g_hs = fp16(feats * srcnorm[row]) ----------------
__global__ void k_prescale(const float* __restrict__ feats, int n4) {
    int i = blockIdx.x * blockDim.x + threadIdx.x;   // over NN*DD/4
    if (i >= n4) return;
    int base = i * 4;
    int row = base >> 7;
    float s = g_srcnorm[row];
    float4 v = ((const float4*)feats)[i];
    __half2 h0 = __floats2half2_rn(v.x * s, v.y * s);
    __half2 h1 = __floats2half2_rn(v.z * s, v.w * s);
    ((__half2*)g_hs)[i * 2]     = h0;
    ((__half2*)g_hs)[i * 2 + 1] = h1;
}

// ---------------- CSR aggregation (fp16 gather -> fp32, x dstnorm) -----------
// one warp per dst node; lane handles 4 feature values (8 bytes fp16)
__global__ void __launch_bounds__(256)
agg_kernel(int n) {
    int w = blockIdx.x * 8 + (threadIdx.x >> 5);
    if (w >= n) return;
    int lane = threadIdx.x & 31;

    int start = g_off[w];
    int end   = g_off[w + 1];

    float4 acc = make_float4(0.f, 0.f, 0.f, 0.f);

    for (int i = start; i < end; i += 32) {
        int myid = (i + lane < end) ? g_csr[i + lane] : 0;
        int cnt = min(32, end - i);
#pragma unroll 4
        for (int j = 0; j < cnt; j++) {
            int s = __shfl_sync(0xffffffffu, myid, j);
            // 4 halfs = 8 bytes per lane, warp reads one coalesced 256B row
            const __half2* p = (const __half2*)&g_hs[(size_t)s * 128 + lane * 4];
            float2 a = __half22float2(p[0]);
            float2 b = __half22float2(p[1]);
            acc.x += a.x; acc.y += a.y; acc.z += b.x; acc.w += b.y;
        }
    }

    float dn = g_dstnorm[w];
    float4 o = make_float4(acc.x * dn, acc.y * dn, acc.z * dn, acc.w * dn);
    *(float4*)&g_t[(size_t)w * 128 + lane * 4] = o;
}

// ---------------- GEMM: h = act(g_t @ W + b) ----------------
// FINAL=0: write g_hs = fp16(relu(h) * srcnorm)   (next layer's gather operand)
// FINAL=1: write out  = h (fp32, no relu, no srcnorm)
// 128x128 tile, 256 threads, 8x8 per thread, BK=16, packed fma.rn.f32x2.
template <int FINAL>
__global__ void __launch_bounds__(256)
gemm_kernel(const float* __restrict__ A, const float* __restrict__ W,
            const float* __restrict__ bias, float* __restrict__ out, int M) {
    __shared__ float As[16][132];
    __shared__ float Bs[16 * 128];

    const int t  = threadIdx.x;
    const int tx = t & 15;
    const int ty = t >> 4;
    const int row0 = blockIdx.x * 128;

    unsigned long long acc2[8][4];
#pragma unroll
    for (int i = 0; i < 8; i++)
#pragma unroll
        for (int j = 0; j < 4; j++) acc2[i][j] = 0ull;

    for (int kk = 0; kk < 128; kk += 16) {
#pragma unroll
        for (int i = 0; i < 8; i++) {
            int idx = t + i * 256;
            int m = idx >> 4, k = idx & 15;
            int gr = row0 + m;
            As[k][m] = (gr < M) ? A[gr * 128 + kk + k] : 0.f;
        }
#pragma unroll
        for (int i = 0; i < 8; i++) {
            int idx = t + i * 256;
            int k = idx >> 7, n = idx & 127;
            Bs[k * 128 + n] = W[(kk + k) * 128 + n];
        }
        __syncthreads();

#pragma unroll
        for (int k = 0; k < 16; k++) {
            float4 a0 = *(const float4*)&As[k][ty * 8];
            float4 a1 = *(const float4*)&As[k][ty * 8 + 4];
            ulonglong2 bq0 = *(const ulonglong2*)&Bs[k * 128 + tx * 4];
            ulonglong2 bq1 = *(const ulonglong2*)&Bs[k * 128 + 64 + tx * 4];
            unsigned long long bp[4] = {bq0.x, bq0.y, bq1.x, bq1.y};

            float av[8] = {a0.x, a0.y, a0.z, a0.w, a1.x, a1.y, a1.z, a1.w};
            unsigned long long ap[8];
#pragma unroll
            for (int i = 0; i < 8; i++)
                asm("mov.b64 %0, {%1, %1};" : "=l"(ap[i]) : "f"(av[i]));

#pragma unroll
            for (int i = 0; i < 8; i++)
#pragma unroll
                for (int j = 0; j < 4; j++)
                    asm("fma.rn.f32x2 %0, %1, %2, %3;"
                        : "=l"(acc2[i][j])
                        : "l"(ap[i]), "l"(bp[j]), "l"(acc2[i][j]));
        }
        __syncthreads();
    }

    // epilogue
    float bv[8];
#pragma unroll
    for (int j = 0; j < 4; j++) bv[j] = bias[tx * 4 + j];
#pragma unroll
    for (int j = 0; j < 4; j++) bv[4 + j] = bias[64 + tx * 4 + j];

#pragma unroll
    for (int i = 0; i < 8; i++) {
        int gr = row0 + ty * 8 + i;
        if (gr < M) {
            float c[8];
#pragma unroll
            for (int j = 0; j < 4; j++)
                asm("mov.b64 {%0, %1}, %2;"
                    : "=f"(c[2 * j]), "=f"(c[2 * j + 1]) : "l"(acc2[i][j]));
            if (FINAL) {
                float4 o0 = make_float4(c[0] + bv[0], c[1] + bv[1],
                                        c[2] + bv[2], c[3] + bv[3]);
                float4 o1 = make_float4(c[4] + bv[4], c[5] + bv[5],
                                        c[6] + bv[6], c[7] + bv[7]);
                *(float4*)&out[(size_t)gr * 128 + tx * 4] = o0;
                *(float4*)&out[(size_t)gr * 128 + 64 + tx * 4] = o1;
            } else {
                float s = g_srcnorm[gr];
                float h[8];
#pragma unroll
                for (int j = 0; j < 8; j++)
                    h[j] = fmaxf(c[j] + bv[j], 0.f) * s;
                __half2 p0 = __floats2half2_rn(h[0], h[1]);
                __half2 p1 = __floats2half2_rn(h[2], h[3]);
                __half2 p2 = __floats2half2_rn(h[4], h[5]);
                __half2 p3 = __floats2half2_rn(h[6], h[7]);
                __half2* d0 = (__half2*)&g_hs[(size_t)gr * 128 + tx * 4];
                __half2* d1 = (__half2*)&g_hs[(size_t)gr * 128 + 64 + tx * 4];
                d0[0] = p0; d0[1] = p1;
                d1[0] = p2; d1[1] = p3;
            }
        }
    }
}

// ---------------- launch ----------------
extern "C" void kernel_launch(void* const* d_in, const int* in_sizes, int n_in,
                              void* d_out, int out_size) {
    const float* feats = (const float*)d_in[0];
    const float* W1 = (const float*)d_in[1];
    const float* b1 = (const float*)d_in[2];
    const float* W2 = (const float*)d_in[3];
    const float* b2 = (const float*)d_in[4];
    const float* W3 = (const float*)d_in[5];
    const float* b3 = (const float*)d_in[6];
    const int* src = (const int*)d_in[7];
    const int* dst = (const int*)d_in[8];
    float* out = (float*)d_out;

    const int M = in_sizes[0] / DD;   // 100000
    const int E = in_sizes[7];        // 1600000

    float* tp = nullptr;
    cudaGetSymbolAddress((void**)&tp, g_t);

    const int nb_node = (M + 255) / 256;
    const int nb_edge = (E + 255) / 256;
    const int nb_gemm = (M + 127) / 128;
    const int nb_agg  = (M + 7) / 8;
    const int nb_vec4 = (M * DD / 4 + 255) / 256;
    const int nscan   = (M + SCAN_B - 1) / SCAN_B;

    // ---- norms + CSR (by dst) ----
    k_zero<<<nb_node, 256>>>(M);
    k_count<<<nb_edge, 256>>>(src, dst, E);
    k_norm<<<nb_node, 256>>>(M);
    k_scan1<<<nscan, SCAN_B>>>(M);
    k_scan2<<<1, 32>>>(nscan, M);
    k_scan3<<<nb_node, 256>>>(M);
    k_fill<<<nb_edge, 256>>>(src, dst, E);

    // ---- layer 0 input: hs = fp16(feats * srcnorm) ----
    k_prescale<<<nb_vec4, 256>>>(feats, M * DD / 4);

    // ---- layer 1: t = agg(hs)*dstnorm ; hs = fp16(relu(tW1+b1)*srcnorm) ----
    agg_kernel<<<nb_agg, 256>>>(M);
    gemm_kernel<0><<<nb_gemm, 256>>>(tp, W1, b1, nullptr, M);
    // ---- layer 2 ----
    agg_kernel<<<nb_agg, 256>>>(M);
    gemm_kernel<0><<<nb_gemm, 256>>>(tp, W2, b2, nullptr, M);
    // ---- layer 3: out = tW3 + b3 (fp32) ----
    agg_kernel<<<nb_agg, 256>>>(M);
    gemm_kernel<1><<<nb_gemm, 256>>>(tp, W3, b3, out, M);
}

// round 6
// speedup vs baseline: 2.2556x; 2.2556x over previous
#include <cuda_runtime.h>
#include <cuda_fp16.h>
#include <cstdint>

#define NN 100000
#define NE 1600000
#define DD 128
#define SCAN_B 512
#define NSCAN ((NN + SCAN_B - 1) / SCAN_B)

// ---------------- scratch (static device globals) ----------------
__device__ float g_hn[NN * DD];     // (h @ W) * src_norm  (messages, fp32)
__device__ float g_h[NN * DD];      // aggregated + transformed activations
__device__ int   g_cin[NN];
__device__ int   g_cout[NN];
__device__ int   g_fill[NN];
__device__ int   g_off[NN + 1];     // CSR row offsets (by dst)
__device__ int   g_csr[NE];         // src ids sorted by dst
__device__ float g_srcnorm[NN];
__device__ float g_dstnorm[NN];
__device__ int   g_bsum[NSCAN];
__device__ int   g_bpre[NSCAN];

// ---------------- CSR build ----------------
__global__ void k_zero(int n) {
    int i = blockIdx.x * blockDim.x + threadIdx.x;
    if (i < n) { g_cin[i] = 0; g_cout[i] = 0; g_fill[i] = 0; }
}

__global__ void k_count(const int* __restrict__ src,
                        const int* __restrict__ dst, int E) {
    int i = blockIdx.x * blockDim.x + threadIdx.x;
    if (i < E) {
        atomicAdd(&g_cout[src[i]], 1);
        atomicAdd(&g_cin[dst[i]], 1);
    }
}

__global__ void k_norm(int n) {
    int i = blockIdx.x * blockDim.x + threadIdx.x;
    if (i < n) {
        g_srcnorm[i] = rsqrtf((float)max(g_cout[i], 1));
        g_dstnorm[i] = rsqrtf((float)max(g_cin[i], 1));
    }
}

__global__ void k_scan1(int n) {
    __shared__ int s[SCAN_B];
    int t = threadIdx.x;
    int g = blockIdx.x * SCAN_B + t;
    int v = (g < n) ? g_cin[g] : 0;
    s[t] = v;
    __syncthreads();
    for (int o = 1; o < SCAN_B; o <<= 1) {
        int x = (t >= o) ? s[t - o] : 0;
        __syncthreads();
        s[t] += x;
        __syncthreads();
    }
    if (g < n) g_off[g] = s[t] - v;
    if (t == SCAN_B - 1) g_bsum[blockIdx.x] = s[t];
}

__global__ void k_scan2(int nb, int n) {
    if (threadIdx.x == 0 && blockIdx.x == 0) {
        int run = 0;
        for (int b = 0; b < nb; b++) { g_bpre[b] = run; run += g_bsum[b]; }
        g_off[n] = run;
    }
}

__global__ void k_scan3(int n) {
    int g = blockIdx.x * blockDim.x + threadIdx.x;
    if (g < n) g_off[g] += g_bpre[g / SCAN_B];
}

__global__ void k_fill(const int* __restrict__ src,
                       const int* __restrict__ dst, int E) {
    int e = blockIdx.x * blockDim.x + threadIdx.x;
    if (e < E) {
        int d = dst[e];
        int p = g_off[d] + atomicAdd(&g_fill[d], 1);
        g_csr[p] = src[e];
    }
}

// ---------------- GEMM: g_hn = (fp16(A) @ fp16(W)) * src_norm ----------------
// HMMA mma.sync m16n8k16, fp32 accumulate. Block 128x128, 8 warps (4M x 2N),
// warp tile 32x64. BK=32 (two k16 steps per stage). A/W quantized to fp16 on
// the smem staging path; everything else fp32.
#define APAD 40    // 32 -> 40 halfs (80B rows: ldmatrix bank-conflict-free)
#define BPAD 136   // 128 -> 136 halfs (272B rows: conflict-free, 16B aligned)

__global__ void __launch_bounds__(256)
gemm_kernel(const float* __restrict__ A, const float* __restrict__ W, int M) {
    __shared__ __half As[128 * APAD];   // [row][k]
    __shared__ __half Bs[32 * BPAD];    // [k][n]

    const int t    = threadIdx.x;
    const int lane = t & 31;
    const int w    = t >> 5;
    const int wm   = w & 3;             // 4 warps in M
    const int wn   = w >> 2;            // 2 warps in N
    const int row0 = blockIdx.x * 128;

    float d[2][8][4];
#pragma unroll
    for (int mt = 0; mt < 2; mt++)
#pragma unroll
        for (int nt = 0; nt < 8; nt++)
#pragma unroll
            for (int r = 0; r < 4; r++) d[mt][nt][r] = 0.f;

    for (int kk = 0; kk < 128; kk += 32) {
        // stage A tile (128 x 32) fp32 -> fp16
#pragma unroll
        for (int i = 0; i < 4; i++) {
            int f = t + i * 256;              // 1024 float4s
            int row = f >> 3, c4 = f & 7;     // 8 float4 per row
            int gr = row0 + row;
            float4 v = (gr < M) ? *(const float4*)&A[(size_t)gr * 128 + kk + c4 * 4]
                                : make_float4(0.f, 0.f, 0.f, 0.f);
            __half2 h0 = __floats2half2_rn(v.x, v.y);
            __half2 h1 = __floats2half2_rn(v.z, v.w);
            __half2* p = (__half2*)&As[row * APAD + c4 * 4];
            p[0] = h0; p[1] = h1;
        }
        // stage W tile (32 x 128) fp32 -> fp16
#pragma unroll
        for (int i = 0; i < 4; i++) {
            int f = t + i * 256;              // 1024 float4s
            int k = f >> 5, c4 = f & 31;      // 32 float4 per row
            float4 v = *(const float4*)&W[(size_t)(kk + k) * 128 + c4 * 4];
            __half2 h0 = __floats2half2_rn(v.x, v.y);
            __half2 h1 = __floats2half2_rn(v.z, v.w);
            __half2* p = (__half2*)&Bs[k * BPAD + c4 * 4];
            p[0] = h0; p[1] = h1;
        }
        __syncthreads();

#pragma unroll
        for (int ks = 0; ks < 32; ks += 16) {
            // A fragments: 2 ldmatrix.x4 (16x16 each)
            unsigned af[2][4];
#pragma unroll
            for (int mt = 0; mt < 2; mt++) {
                int r = wm * 32 + mt * 16 + (lane & 15);
                int kb = ks + ((lane >> 4) << 3);           // +8 cols for lanes 16-31
                unsigned addr = (unsigned)__cvta_generic_to_shared(&As[r * APAD + kb]);
                asm volatile("ldmatrix.sync.aligned.m8n8.x4.shared.b16 {%0,%1,%2,%3}, [%4];"
                             : "=r"(af[mt][0]), "=r"(af[mt][1]),
                               "=r"(af[mt][2]), "=r"(af[mt][3]) : "r"(addr));
            }
            // B fragments: 8 ldmatrix.x2.trans (16x8 each)
            unsigned bf[8][2];
#pragma unroll
            for (int nt = 0; nt < 8; nt++) {
                int krow = ks + (lane & 15);
                int n0 = wn * 64 + nt * 8;
                unsigned addr = (unsigned)__cvta_generic_to_shared(&Bs[krow * BPAD + n0]);
                asm volatile("ldmatrix.sync.aligned.m8n8.x2.trans.shared.b16 {%0,%1}, [%2];"
                             : "=r"(bf[nt][0]), "=r"(bf[nt][1]) : "r"(addr));
            }
#pragma unroll
            for (int mt = 0; mt < 2; mt++)
#pragma unroll
                for (int nt = 0; nt < 8; nt++)
                    asm volatile(
                        "mma.sync.aligned.m16n8k16.row.col.f32.f16.f16.f32 "
                        "{%0,%1,%2,%3}, {%4,%5,%6,%7}, {%8,%9}, {%0,%1,%2,%3};"
                        : "+f"(d[mt][nt][0]), "+f"(d[mt][nt][1]),
                          "+f"(d[mt][nt][2]), "+f"(d[mt][nt][3])
                        : "r"(af[mt][0]), "r"(af[mt][1]),
                          "r"(af[mt][2]), "r"(af[mt][3]),
                          "r"(bf[nt][0]), "r"(bf[nt][1]));
        }
        __syncthreads();
    }

    // epilogue: scale rows by src_norm, write fp32 messages
#pragma unroll
    for (int mt = 0; mt < 2; mt++) {
        int gr0 = row0 + wm * 32 + mt * 16 + (lane >> 2);
        int gr1 = gr0 + 8;
        float s0 = (gr0 < M) ? g_srcnorm[gr0] : 0.f;
        float s1 = (gr1 < M) ? g_srcnorm[gr1] : 0.f;
#pragma unroll
        for (int nt = 0; nt < 8; nt++) {
            int gc = wn * 64 + nt * 8 + ((lane & 3) << 1);
            if (gr0 < M) {
                float2 o = make_float2(d[mt][nt][0] * s0, d[mt][nt][1] * s0);
                *(float2*)&g_hn[(size_t)gr0 * 128 + gc] = o;
            }
            if (gr1 < M) {
                float2 o = make_float2(d[mt][nt][2] * s1, d[mt][nt][3] * s1);
                *(float2*)&g_hn[(size_t)gr1 * 128 + gc] = o;
            }
        }
    }
}

// ---------------- CSR aggregation: one warp per dst node (fp32 gather) ------
template <int RELU>
__global__ void __launch_bounds__(256)
agg_kernel(const float* __restrict__ bias, float* __restrict__ out, int n) {
    int w = blockIdx.x * 8 + (threadIdx.x >> 5);
    if (w >= n) return;
    int lane = threadIdx.x & 31;

    int start = g_off[w];
    int end   = g_off[w + 1];

    float4 acc = make_float4(0.f, 0.f, 0.f, 0.f);

    for (int i = start; i < end; i += 32) {
        int myid = (i + lane < end) ? g_csr[i + lane] : 0;
        int cnt = min(32, end - i);
#pragma unroll 4
        for (int j = 0; j < cnt; j++) {
            int s = __shfl_sync(0xffffffffu, myid, j);
            const float4 v = *(const float4*)&g_hn[(size_t)s * 128 + lane * 4];
            acc.x += v.x; acc.y += v.y; acc.z += v.z; acc.w += v.w;
        }
    }

    float dn = g_dstnorm[w];
    float4 b = *(const float4*)&bias[lane * 4];
    float4 o = make_float4(fmaf(acc.x, dn, b.x), fmaf(acc.y, dn, b.y),
                           fmaf(acc.z, dn, b.z), fmaf(acc.w, dn, b.w));
    if (RELU) {
        o.x = fmaxf(o.x, 0.f); o.y = fmaxf(o.y, 0.f);
        o.z = fmaxf(o.z, 0.f); o.w = fmaxf(o.w, 0.f);
    }
    *(float4*)&out[(size_t)w * 128 + lane * 4] = o;
}

// ---------------- launch ----------------
extern "C" void kernel_launch(void* const* d_in, const int* in_sizes, int n_in,
                              void* d_out, int out_size) {
    const float* feats = (const float*)d_in[0];
    const float* W1 = (const float*)d_in[1];
    const float* b1 = (const float*)d_in[2];
    const float* W2 = (const float*)d_in[3];
    const float* b2 = (const float*)d_in[4];
    const float* W3 = (const float*)d_in[5];
    const float* b3 = (const float*)d_in[6];
    const int* src = (const int*)d_in[7];
    const int* dst = (const int*)d_in[8];
    float* out = (float*)d_out;

    const int M = in_sizes[0] / DD;   // 100000
    const int E = in_sizes[7];        // 1600000

    float* hp = nullptr;
    cudaGetSymbolAddress((void**)&hp, g_h);

    const int nb_node = (M + 255) / 256;
    const int nb_edge = (E + 255) / 256;
    const int nb_gemm = (M + 127) / 128;
    const int nb_agg  = (M + 7) / 8;
    const int nscan   = (M + SCAN_B - 1) / SCAN_B;

    // ---- build norms + CSR (by dst) ----
    k_zero<<<nb_node, 256>>>(M);
    k_count<<<nb_edge, 256>>>(src, dst, E);
    k_norm<<<nb_node, 256>>>(M);
    k_scan1<<<nscan, SCAN_B>>>(M);
    k_scan2<<<1, 32>>>(nscan, M);
    k_scan3<<<nb_node, 256>>>(M);
    k_fill<<<nb_edge, 256>>>(src, dst, E);

    // ---- layer 1 ----
    gemm_kernel<<<nb_gemm, 256>>>(feats, W1, M);
    agg_kernel<1><<<nb_agg, 256>>>(b1, hp, M);
    // ---- layer 2 ----
    gemm_kernel<<<nb_gemm, 256>>>(hp, W2, M);
    agg_kernel<1><<<nb_agg, 256>>>(b2, hp, M);
    // ---- layer 3 ----
    gemm_kernel<<<nb_gemm, 256>>>(hp, W3, M);
    agg_kernel<0><<<nb_agg, 256>>>(b3, out, M);
}

// round 7
// speedup vs baseline: 2.6171x; 1.1603x over previous
#include <cuda_runtime.h>
#include <cuda_fp16.h>
#include <cstdint>

#define NN 100000
#define NE 1600000
#define DD 128
#define SCAN_B 512
#define NSCAN ((NN + SCAN_B - 1) / SCAN_B)

// ---------------- scratch (static device globals) ----------------
__device__ __half g_hn[NN * DD];    // (h @ W) * src_norm  (messages, fp16)
__device__ __half g_h[NN * DD];     // aggregated activations, fp16 (GEMM-A operand)
__device__ int    g_cin[NN];
__device__ int    g_cout[NN];
__device__ int    g_fill[NN];
__device__ int    g_off[NN + 1];    // CSR row offsets (by dst)
__device__ int    g_csr[NE];        // src ids sorted by dst
__device__ float  g_srcnorm[NN];
__device__ float  g_dstnorm[NN];
__device__ int    g_bsum[NSCAN];
__device__ int    g_bpre[NSCAN];

// ---------------- CSR build ----------------
__global__ void k_zero(int n) {
    int i = blockIdx.x * blockDim.x + threadIdx.x;
    if (i < n) { g_cin[i] = 0; g_cout[i] = 0; g_fill[i] = 0; }
}

__global__ void k_count(const int* __restrict__ src,
                        const int* __restrict__ dst, int E) {
    int i = blockIdx.x * blockDim.x + threadIdx.x;
    if (i < E) {
        atomicAdd(&g_cout[src[i]], 1);
        atomicAdd(&g_cin[dst[i]], 1);
    }
}

__global__ void k_norm(int n) {
    int i = blockIdx.x * blockDim.x + threadIdx.x;
    if (i < n) {
        g_srcnorm[i] = rsqrtf((float)max(g_cout[i], 1));
        g_dstnorm[i] = rsqrtf((float)max(g_cin[i], 1));
    }
}

__global__ void k_scan1(int n) {
    __shared__ int s[SCAN_B];
    int t = threadIdx.x;
    int g = blockIdx.x * SCAN_B + t;
    int v = (g < n) ? g_cin[g] : 0;
    s[t] = v;
    __syncthreads();
    for (int o = 1; o < SCAN_B; o <<= 1) {
        int x = (t >= o) ? s[t - o] : 0;
        __syncthreads();
        s[t] += x;
        __syncthreads();
    }
    if (g < n) g_off[g] = s[t] - v;
    if (t == SCAN_B - 1) g_bsum[blockIdx.x] = s[t];
}

__global__ void k_scan2(int nb, int n) {
    if (threadIdx.x == 0 && blockIdx.x == 0) {
        int run = 0;
        for (int b = 0; b < nb; b++) { g_bpre[b] = run; run += g_bsum[b]; }
        g_off[n] = run;
    }
}

__global__ void k_scan3(int n) {
    int g = blockIdx.x * blockDim.x + threadIdx.x;
    if (g < n) g_off[g] += g_bpre[g / SCAN_B];
}

__global__ void k_fill(const int* __restrict__ src,
                       const int* __restrict__ dst, int E) {
    int e = blockIdx.x * blockDim.x + threadIdx.x;
    if (e < E) {
        int d = dst[e];
        int p = g_off[d] + atomicAdd(&g_fill[d], 1);
        g_csr[p] = src[e];
    }
}

// ---------------- GEMM: g_hn = fp16( (fp16(A) @ fp16(W)) * src_norm ) --------
// HMMA mma.sync m16n8k16, fp32 accumulate. Block 128x128, 8 warps (4M x 2N),
// warp tile 32x64, BK=32. A staged from fp32 (layer 1) or fp16 (layers 2-3).
#define APAD 40    // 32 -> 40 halfs (80B rows: ldmatrix bank-conflict-free)
#define BPAD 136   // 128 -> 136 halfs (272B rows: conflict-free, 16B aligned)

template <typename TA>
__global__ void __launch_bounds__(256)
gemm_kernel(const TA* __restrict__ A, const float* __restrict__ W, int M) {
    __shared__ __half As[128 * APAD];   // [row][k]
    __shared__ __half Bs[32 * BPAD];    // [k][n]

    const int t    = threadIdx.x;
    const int lane = t & 31;
    const int w    = t >> 5;
    const int wm   = w & 3;
    const int wn   = w >> 2;
    const int row0 = blockIdx.x * 128;

    float d[2][8][4];
#pragma unroll
    for (int mt = 0; mt < 2; mt++)
#pragma unroll
        for (int nt = 0; nt < 8; nt++)
#pragma unroll
            for (int r = 0; r < 4; r++) d[mt][nt][r] = 0.f;

    for (int kk = 0; kk < 128; kk += 32) {
        // ---- stage A tile (128 x 32) ----
        if constexpr (sizeof(TA) == 4) {
            // fp32 -> fp16 convert
#pragma unroll
            for (int i = 0; i < 4; i++) {
                int f = t + i * 256;              // 1024 float4s
                int row = f >> 3, c4 = f & 7;
                int gr = row0 + row;
                float4 v = (gr < M) ? *(const float4*)&A[(size_t)gr * 128 + kk + c4 * 4]
                                    : make_float4(0.f, 0.f, 0.f, 0.f);
                __half2 h0 = __floats2half2_rn(v.x, v.y);
                __half2 h1 = __floats2half2_rn(v.z, v.w);
                __half2* p = (__half2*)&As[row * APAD + c4 * 4];
                p[0] = h0; p[1] = h1;
            }
        } else {
            // direct fp16 copy, 8 halfs (16B) per thread-chunk
#pragma unroll
            for (int i = 0; i < 2; i++) {
                int f = t + i * 256;              // 512 uint4s
                int row = f >> 2, c8 = f & 3;     // 4 x 8-half chunks per row
                int gr = row0 + row;
                uint4 v = (gr < M)
                    ? *(const uint4*)&A[(size_t)gr * 128 + kk + c8 * 8]
                    : make_uint4(0u, 0u, 0u, 0u);
                *(uint4*)&As[row * APAD + c8 * 8] = v;
            }
        }
        // ---- stage W tile (32 x 128), fp32 -> fp16 ----
#pragma unroll
        for (int i = 0; i < 4; i++) {
            int f = t + i * 256;
            int k = f >> 5, c4 = f & 31;
            float4 v = *(const float4*)&W[(size_t)(kk + k) * 128 + c4 * 4];
            __half2 h0 = __floats2half2_rn(v.x, v.y);
            __half2 h1 = __floats2half2_rn(v.z, v.w);
            __half2* p = (__half2*)&Bs[k * BPAD + c4 * 4];
            p[0] = h0; p[1] = h1;
        }
        __syncthreads();

#pragma unroll
        for (int ks = 0; ks < 32; ks += 16) {
            unsigned af[2][4];
#pragma unroll
            for (int mt = 0; mt < 2; mt++) {
                int r = wm * 32 + mt * 16 + (lane & 15);
                int kb = ks + ((lane >> 4) << 3);
                unsigned addr = (unsigned)__cvta_generic_to_shared(&As[r * APAD + kb]);
                asm volatile("ldmatrix.sync.aligned.m8n8.x4.shared.b16 {%0,%1,%2,%3}, [%4];"
                             : "=r"(af[mt][0]), "=r"(af[mt][1]),
                               "=r"(af[mt][2]), "=r"(af[mt][3]) : "r"(addr));
            }
            unsigned bf[8][2];
#pragma unroll
            for (int nt = 0; nt < 8; nt++) {
                int krow = ks + (lane & 15);
                int n0 = wn * 64 + nt * 8;
                unsigned addr = (unsigned)__cvta_generic_to_shared(&Bs[krow * BPAD + n0]);
                asm volatile("ldmatrix.sync.aligned.m8n8.x2.trans.shared.b16 {%0,%1}, [%2];"
                             : "=r"(bf[nt][0]), "=r"(bf[nt][1]) : "r"(addr));
            }
#pragma unroll
            for (int mt = 0; mt < 2; mt++)
#pragma unroll
                for (int nt = 0; nt < 8; nt++)
                    asm volatile(
                        "mma.sync.aligned.m16n8k16.row.col.f32.f16.f16.f32 "
                        "{%0,%1,%2,%3}, {%4,%5,%6,%7}, {%8,%9}, {%0,%1,%2,%3};"
                        : "+f"(d[mt][nt][0]), "+f"(d[mt][nt][1]),
                          "+f"(d[mt][nt][2]), "+f"(d[mt][nt][3])
                        : "r"(af[mt][0]), "r"(af[mt][1]),
                          "r"(af[mt][2]), "r"(af[mt][3]),
                          "r"(bf[nt][0]), "r"(bf[nt][1]));
        }
        __syncthreads();
    }

    // epilogue: scale rows by src_norm, write fp16 messages
#pragma unroll
    for (int mt = 0; mt < 2; mt++) {
        int gr0 = row0 + wm * 32 + mt * 16 + (lane >> 2);
        int gr1 = gr0 + 8;
        float s0 = (gr0 < M) ? g_srcnorm[gr0] : 0.f;
        float s1 = (gr1 < M) ? g_srcnorm[gr1] : 0.f;
#pragma unroll
        for (int nt = 0; nt < 8; nt++) {
            int gc = wn * 64 + nt * 8 + ((lane & 3) << 1);
            if (gr0 < M)
                *(__half2*)&g_hn[(size_t)gr0 * 128 + gc] =
                    __floats2half2_rn(d[mt][nt][0] * s0, d[mt][nt][1] * s0);
            if (gr1 < M)
                *(__half2*)&g_hn[(size_t)gr1 * 128 + gc] =
                    __floats2half2_rn(d[mt][nt][2] * s1, d[mt][nt][3] * s1);
        }
    }
}

// ---------------- CSR aggregation: one warp per dst node --------------------
// fp16 gather (one LDG.64 per lane = 4 halfs), fp32 accumulate.
// FINAL=0: g_h = fp16(relu(acc*dstnorm + bias));  FINAL=1: out fp32, no relu.
template <int FINAL>
__global__ void __launch_bounds__(256)
agg_kernel(const float* __restrict__ bias, float* __restrict__ out, int n) {
    int w = blockIdx.x * 8 + (threadIdx.x >> 5);
    if (w >= n) return;
    int lane = threadIdx.x & 31;

    int start = g_off[w];
    int end   = g_off[w + 1];

    float4 acc = make_float4(0.f, 0.f, 0.f, 0.f);

    for (int i = start; i < end; i += 32) {
        int myid = (i + lane < end) ? g_csr[i + lane] : 0;
        int cnt = min(32, end - i);
#pragma unroll 4
        for (int j = 0; j < cnt; j++) {
            int s = __shfl_sync(0xffffffffu, myid, j);
            uint2 v = *(const uint2*)&g_hn[(size_t)s * 128 + lane * 4];
            float2 a = __half22float2(*(__half2*)&v.x);
            float2 b = __half22float2(*(__half2*)&v.y);
            acc.x += a.x; acc.y += a.y; acc.z += b.x; acc.w += b.y;
        }
    }

    float dn = g_dstnorm[w];
    float4 b = *(const float4*)&bias[lane * 4];
    float4 o = make_float4(fmaf(acc.x, dn, b.x), fmaf(acc.y, dn, b.y),
                           fmaf(acc.z, dn, b.z), fmaf(acc.w, dn, b.w));
    if (FINAL) {
        *(float4*)&out[(size_t)w * 128 + lane * 4] = o;
    } else {
        o.x = fmaxf(o.x, 0.f); o.y = fmaxf(o.y, 0.f);
        o.z = fmaxf(o.z, 0.f); o.w = fmaxf(o.w, 0.f);
        uint2 p;
        *(__half2*)&p.x = __floats2half2_rn(o.x, o.y);
        *(__half2*)&p.y = __floats2half2_rn(o.z, o.w);
        *(uint2*)&g_h[(size_t)w * 128 + lane * 4] = p;
    }
}

// ---------------- launch ----------------
extern "C" void kernel_launch(void* const* d_in, const int* in_sizes, int n_in,
                              void* d_out, int out_size) {
    const float* feats = (const float*)d_in[0];
    const float* W1 = (const float*)d_in[1];
    const float* b1 = (const float*)d_in[2];
    const float* W2 = (const float*)d_in[3];
    const float* b2 = (const float*)d_in[4];
    const float* W3 = (const float*)d_in[5];
    const float* b3 = (const float*)d_in[6];
    const int* src = (const int*)d_in[7];
    const int* dst = (const int*)d_in[8];
    float* out = (float*)d_out;

    const int M = in_sizes[0] / DD;   // 100000
    const int E = in_sizes[7];        // 1600000

    __half* hp = nullptr;
    cudaGetSymbolAddress((void**)&hp, g_h);

    const int nb_node = (M + 255) / 256;
    const int nb_edge = (E + 255) / 256;
    const int nb_gemm = (M + 127) / 128;
    const int nb_agg  = (M + 7) / 8;
    const int nscan   = (M + SCAN_B - 1) / SCAN_B;

    // ---- build norms + CSR (by dst) ----
    k_zero<<<nb_node, 256>>>(M);
    k_count<<<nb_edge, 256>>>(src, dst, E);
    k_norm<<<nb_node, 256>>>(M);
    k_scan1<<<nscan, SCAN_B>>>(M);
    k_scan2<<<1, 32>>>(nscan, M);
    k_scan3<<<nb_node, 256>>>(M);
    k_fill<<<nb_edge, 256>>>(src, dst, E);

    // ---- layer 1 ----
    gemm_kernel<float><<<nb_gemm, 256>>>(feats, W1, M);
    agg_kernel<0><<<nb_agg, 256>>>(b1, nullptr, M);
    // ---- layer 2 ----
    gemm_kernel<__half><<<nb_gemm, 256>>>(hp, W2, M);
    agg_kernel<0><<<nb_agg, 256>>>(b2, nullptr, M);
    // ---- layer 3 ----
    gemm_kernel<__half><<<nb_gemm, 256>>>(hp, W3, M);
    agg_kernel<1><<<nb_agg, 256>>>(b3, out, M);
}